// round 5
// baseline (speedup 1.0000x reference)
#include <cuda_runtime.h>
#include <math.h>
#include <stdint.h>

// ---------------------------------------------------------------------------
// HashMoELayer: shared SwiGLU expert + 2x hash-routed GELU experts (E=8).
// Routing hash (tok*11 + k*7919) % 8 depends only on tok mod 8:
//   k=0: expert e = (3*r) % 8     for tokens tok ≡ r (mod 8)
//   k=1: expert e = (3*r + 7) % 8
// => each expert group is a stride-8 arithmetic progression of tokens.
// ---------------------------------------------------------------------------

#define BM 128
#define BN 128
#define BK 16
#define TM 8
#define TN 8
// 256 threads: (BM/TM)*(BN/TN)

// Problem constants
#define NTOK  32768   // B*T
#define CDIM  1024
#define HS    2048
#define HR    1024
#define MPG   4096    // tokens per expert group (NTOK/8)

// Scratch (device globals; no allocation allowed)
__device__ float g_g1[(size_t)NTOK * HS];   // x@sw1+sb1, then silu*g3 in place
__device__ float g_g3[(size_t)NTOK * HS];   // x@sw3+sb3
__device__ float g_h [(size_t)NTOK * HR];   // routed hidden (grouped order), reused for k=0,1

// MODE:
//  0 : C[row]        = acc + bias                         (plain)
//  2 : C[row]        = 0.5f*(acc + bias)                  (shared-expert output, full store)
//  3 : C[g*M + row]  = gelu(acc + bias), A gathered rows  token = g + 8*(m0+row)
//  4 : C[g + 8*row] += 0.25f*(acc + bias), A contiguous grouped rows
template<int MODE>
__global__ void __launch_bounds__(256, 2)
gemm_k(int M, int N, int K,
       const float* __restrict__ A,
       const float* __restrict__ B,
       const float* __restrict__ bias,
       float* __restrict__ C,
       int phase7)
{
    __shared__ float As[BK][BM];
    __shared__ float Bs[BK][BN];

    const int tid = threadIdx.x;
    const int grp = blockIdx.z;
    const int m0  = blockIdx.y * BM;
    const int n0  = blockIdx.x * BN;

    const float* Bp    = B;
    const float* biasp = bias;
    if (MODE == 3 || MODE == 4) {
        int e = (3 * grp + phase7) & 7;
        Bp    = B    + (size_t)e * K * N;
        biasp = bias + (size_t)e * N;
    }

    // ---- global->shared loaders ----
    const int ar = tid >> 1;            // 0..127 (A tile row)
    const int ac = (tid & 1) * 8;       // 0 or 8 (A tile k-offset)
    size_t a_row_g;
    if      (MODE == 3) a_row_g = (size_t)grp + 8u * (size_t)(m0 + ar);
    else if (MODE == 4) a_row_g = (size_t)grp * M + (size_t)(m0 + ar);
    else                a_row_g = (size_t)(m0 + ar);
    const float* Arow = A + a_row_g * (size_t)K + ac;

    const int br = tid >> 5;            // 0..7
    const int bc = (tid & 31) * 4;      // 0..124
    const float* Bpos = Bp + (size_t)br * N + n0 + bc;

    float acc[TM][TN];
    #pragma unroll
    for (int i = 0; i < TM; i++)
        #pragma unroll
        for (int j = 0; j < TN; j++) acc[i][j] = 0.f;

    const int ty = tid >> 4;   // 0..15 (m)
    const int tx = tid & 15;   // 0..15 (n)

    for (int k0 = 0; k0 < K; k0 += BK) {
        float4 a0 = *(const float4*)(Arow + k0);
        float4 a1 = *(const float4*)(Arow + k0 + 4);
        As[ac + 0][ar] = a0.x; As[ac + 1][ar] = a0.y;
        As[ac + 2][ar] = a0.z; As[ac + 3][ar] = a0.w;
        As[ac + 4][ar] = a1.x; As[ac + 5][ar] = a1.y;
        As[ac + 6][ar] = a1.z; As[ac + 7][ar] = a1.w;

        *(float4*)&Bs[br    ][bc] = *(const float4*)(Bpos + (size_t)k0 * N);
        *(float4*)&Bs[br + 8][bc] = *(const float4*)(Bpos + (size_t)(k0 + 8) * N);

        __syncthreads();

        #pragma unroll
        for (int kk = 0; kk < BK; kk++) {
            float af[TM], bf[TN];
            *(float4*)&af[0] = *(const float4*)&As[kk][ty * TM];
            *(float4*)&af[4] = *(const float4*)&As[kk][ty * TM + 4];
            *(float4*)&bf[0] = *(const float4*)&Bs[kk][tx * TN];
            *(float4*)&bf[4] = *(const float4*)&Bs[kk][tx * TN + 4];
            #pragma unroll
            for (int i = 0; i < TM; i++)
                #pragma unroll
                for (int j = 0; j < TN; j++)
                    acc[i][j] += af[i] * bf[j];
        }
        __syncthreads();
    }

    // ---- epilogue ----
    float bv[TN];
    *(float4*)&bv[0] = *(const float4*)(biasp + n0 + tx * TN);
    *(float4*)&bv[4] = *(const float4*)(biasp + n0 + tx * TN + 4);

    #pragma unroll
    for (int i = 0; i < TM; i++) {
        const int rl = ty * TM + i;  // local row in tile
        size_t crow;
        if      (MODE == 3) crow = (size_t)grp * M + (size_t)(m0 + rl);
        else if (MODE == 4) crow = (size_t)grp + 8u * (size_t)(m0 + rl);
        else                crow = (size_t)(m0 + rl);
        float* Cp = C + crow * (size_t)N + n0 + tx * TN;

        float v[TN];
        #pragma unroll
        for (int j = 0; j < TN; j++) v[j] = acc[i][j] + bv[j];

        if (MODE == 4) {
            float4 c0 = *(float4*)Cp;
            float4 c1 = *(float4*)(Cp + 4);
            c0.x += 0.25f * v[0]; c0.y += 0.25f * v[1];
            c0.z += 0.25f * v[2]; c0.w += 0.25f * v[3];
            c1.x += 0.25f * v[4]; c1.y += 0.25f * v[5];
            c1.z += 0.25f * v[6]; c1.w += 0.25f * v[7];
            *(float4*)Cp       = c0;
            *(float4*)(Cp + 4) = c1;
        } else {
            #pragma unroll
            for (int j = 0; j < TN; j++) {
                if (MODE == 2) v[j] = 0.5f * v[j];
                if (MODE == 3) v[j] = 0.5f * v[j] * (1.0f + erff(v[j] * 0.70710678118654752f));
            }
            float4 o0 = make_float4(v[0], v[1], v[2], v[3]);
            float4 o1 = make_float4(v[4], v[5], v[6], v[7]);
            *(float4*)Cp       = o0;
            *(float4*)(Cp + 4) = o1;
        }
    }
}

// g1 = silu(g1) * g3, elementwise (float4)
__global__ void __launch_bounds__(256)
silu_mul_k(float* __restrict__ g1, const float* __restrict__ g3, size_t n4)
{
    size_t i = (size_t)blockIdx.x * blockDim.x + threadIdx.x;
    if (i < n4) {
        float4 a = ((float4*)g1)[i];
        float4 b = ((const float4*)g3)[i];
        a.x = (a.x / (1.f + expf(-a.x))) * b.x;
        a.y = (a.y / (1.f + expf(-a.y))) * b.y;
        a.z = (a.z / (1.f + expf(-a.z))) * b.z;
        a.w = (a.w / (1.f + expf(-a.w))) * b.w;
        ((float4*)g1)[i] = a;
    }
}

extern "C" void kernel_launch(void* const* d_in, const int* in_sizes, int n_in,
                              void* d_out, int out_size)
{
    const float* x   = (const float*)d_in[0];
    // d_in[1] = t_emb (unused by the reference)
    const float* sw1 = (const float*)d_in[2];
    const float* sb1 = (const float*)d_in[3];
    const float* sw3 = (const float*)d_in[4];
    const float* sb3 = (const float*)d_in[5];
    const float* sw2 = (const float*)d_in[6];
    const float* sb2 = (const float*)d_in[7];
    const float* w1  = (const float*)d_in[8];
    const float* b1  = (const float*)d_in[9];
    const float* w2  = (const float*)d_in[10];
    const float* b2  = (const float*)d_in[11];
    float* out = (float*)d_out;

    float *g1p, *g3p, *hp;
    cudaGetSymbolAddress((void**)&g1p, g_g1);
    cudaGetSymbolAddress((void**)&g3p, g_g3);
    cudaGetSymbolAddress((void**)&hp,  g_h);

    const dim3 blk(256);

    // Shared SwiGLU: g1 = x@sw1+sb1 ; g3 = x@sw3+sb3
    gemm_k<0><<<dim3(HS / BN, NTOK / BM, 1), blk>>>(NTOK, HS, CDIM, x, sw1, sb1, g1p, 0);
    gemm_k<0><<<dim3(HS / BN, NTOK / BM, 1), blk>>>(NTOK, HS, CDIM, x, sw3, sb3, g3p, 0);

    // g1 = silu(g1)*g3
    const size_t n4 = (size_t)NTOK * HS / 4;
    silu_mul_k<<<(unsigned)((n4 + 255) / 256), blk>>>(g1p, g3p, n4);

    // out = 0.5*(g1@sw2 + sb2)   (writes every output element)
    gemm_k<2><<<dim3(CDIM / BN, NTOK / BM, 1), blk>>>(NTOK, CDIM, HS, g1p, sw2, sb2, out, 0);

    // Routed experts, k = 0 (phase 0) and k = 1 (phase 7)
    for (int phase = 0; phase <= 7; phase += 7) {
        // h = gelu(gather(x) @ w1[e] + b1[e]) ; grouped over 8 residue classes
        gemm_k<3><<<dim3(HR / BN, MPG / BM, 8), blk>>>(MPG, HR, CDIM, x, w1, b1, hp, phase);
        // out[token] += 0.25*(h @ w2[e] + b2[e])
        gemm_k<4><<<dim3(CDIM / BN, MPG / BM, 8), blk>>>(MPG, CDIM, HR, hp, w2, b2, out, phase);
    }
}

// round 10
// speedup vs baseline: 1.2897x; 1.2897x over previous
#include <cuda_runtime.h>
#include <math.h>
#include <stdint.h>
#include <mma.h>

using namespace nvcuda;

// ---------------------------------------------------------------------------
// HashMoELayer: shared SwiGLU expert + 2x hash-routed GELU experts (E=8).
// Routing hash (tok*11 + k*7919) % 8 depends only on tok mod 8:
//   k=0: expert e = (3*r) % 8,  k=1: expert e = (3*r + 7) % 8
// => each expert group is an exact stride-8 arithmetic progression of tokens.
// All GEMMs run on tensor cores in tf32 (wmma m16n16k8), fp32 accumulate.
// R10 fix: epilogue staging ldm 17 -> 20 (wmma requires ldm % 4 == 0).
// ---------------------------------------------------------------------------

#define BM 128
#define BN 128
#define BK 32
// 8 warps: 4 (m) x 2 (n); warp tile 32x64 = 2x4 fragments of 16x16

// Problem constants
#define NTOK  32768   // B*T
#define CDIM  1024
#define HS    2048
#define HR    1024
#define MPG   4096    // tokens per expert group (NTOK/8)

#define STLD  20      // staging leading dim: MUST be multiple of 4 for wmma

// Scratch (device globals; no allocation allowed)
__device__ float g_g1[(size_t)NTOK * HS];
__device__ float g_g3[(size_t)NTOK * HS];
__device__ float g_h [(size_t)NTOK * HR];

// MODE:
//  0 : C[row]        = acc + bias
//  2 : C[row]        = 0.5f*(acc + bias)
//  3 : C[g*M + row]  = gelu(acc + bias), A gathered: token = g + 8*(m0+row)
//  4 : C[g + 8*row] += 0.25f*(acc + bias), A contiguous grouped rows
template<int MODE>
__global__ void __launch_bounds__(256, 2)
gemm_tc(int M, int N, int K,
        const float* __restrict__ A,
        const float* __restrict__ B,
        const float* __restrict__ bias,
        float* __restrict__ C,
        int phase7)
{
    __shared__ float As[BM][BK + 4];        // 128 x 36
    __shared__ float Bs[BK][BN + 4];        // 32 x 132
    __shared__ float St[8][16][STLD];       // per-warp epilogue staging

    const int tid  = threadIdx.x;
    const int wid  = tid >> 5;
    const int lane = tid & 31;
    const int wm   = wid >> 1;           // 0..3  (32-row slab)
    const int wn   = wid & 1;            // 0..1  (64-col slab)

    const int grp = blockIdx.z;
    const int m0  = blockIdx.y * BM;
    const int n0  = blockIdx.x * BN;

    const float* Bp    = B;
    const float* biasp = bias;
    if (MODE == 3 || MODE == 4) {
        int e = (3 * grp + phase7) & 7;
        Bp    = B    + (size_t)e * K * N;
        biasp = bias + (size_t)e * N;
    }

    // ---- global->shared loader setup ----
    // A: 128x32 tile, 2 threads/row, 16 floats each
    const int ar = tid >> 1;
    const int ac = (tid & 1) * 16;
    size_t a_row_g;
    if      (MODE == 3) a_row_g = (size_t)grp + 8u * (size_t)(m0 + ar);
    else if (MODE == 4) a_row_g = (size_t)grp * M + (size_t)(m0 + ar);
    else                a_row_g = (size_t)(m0 + ar);
    const float* Arow = A + a_row_g * (size_t)K + ac;

    // B: 32x128 tile, 8 threads/row, 16 floats each
    const int br = tid >> 3;
    const int bc = (tid & 7) * 16;
    const float* Bpos = Bp + (size_t)br * N + n0 + bc;

    wmma::fragment<wmma::accumulator, 16, 16, 8, float> acc[2][4];
    #pragma unroll
    for (int i = 0; i < 2; i++)
        #pragma unroll
        for (int j = 0; j < 4; j++) wmma::fill_fragment(acc[i][j], 0.0f);

    for (int k0 = 0; k0 < K; k0 += BK) {
        // stage A (convert to tf32 bits)
        #pragma unroll
        for (int q = 0; q < 4; q++) {
            float4 v = *(const float4*)(Arow + k0 + q * 4);
            As[ar][ac + q * 4 + 0] = wmma::__float_to_tf32(v.x);
            As[ar][ac + q * 4 + 1] = wmma::__float_to_tf32(v.y);
            As[ar][ac + q * 4 + 2] = wmma::__float_to_tf32(v.z);
            As[ar][ac + q * 4 + 3] = wmma::__float_to_tf32(v.w);
        }
        // stage B
        #pragma unroll
        for (int q = 0; q < 4; q++) {
            float4 v = *(const float4*)(Bpos + (size_t)k0 * N + q * 4);
            Bs[br][bc + q * 4 + 0] = wmma::__float_to_tf32(v.x);
            Bs[br][bc + q * 4 + 1] = wmma::__float_to_tf32(v.y);
            Bs[br][bc + q * 4 + 2] = wmma::__float_to_tf32(v.z);
            Bs[br][bc + q * 4 + 3] = wmma::__float_to_tf32(v.w);
        }
        __syncthreads();

        #pragma unroll
        for (int kk = 0; kk < BK / 8; kk++) {
            wmma::fragment<wmma::matrix_a, 16, 16, 8, wmma::precision::tf32, wmma::row_major> af[2];
            wmma::fragment<wmma::matrix_b, 16, 16, 8, wmma::precision::tf32, wmma::row_major> bf[4];
            #pragma unroll
            for (int i = 0; i < 2; i++)
                wmma::load_matrix_sync(af[i], &As[wm * 32 + i * 16][kk * 8], BK + 4);
            #pragma unroll
            for (int j = 0; j < 4; j++)
                wmma::load_matrix_sync(bf[j], &Bs[kk * 8][wn * 64 + j * 16], BN + 4);
            #pragma unroll
            for (int i = 0; i < 2; i++)
                #pragma unroll
                for (int j = 0; j < 4; j++)
                    wmma::mma_sync(acc[i][j], af[i], bf[j], acc[i][j]);
        }
        __syncthreads();
    }

    // ---- epilogue: per-fragment staging through smem ----
    const int sr = lane >> 1;            // 0..15 staging row
    const int sc = (lane & 1) * 8;       // 0 or 8

    #pragma unroll
    for (int i = 0; i < 2; i++) {
        #pragma unroll
        for (int j = 0; j < 4; j++) {
            wmma::store_matrix_sync(&St[wid][0][0], acc[i][j], STLD, wmma::mem_row_major);
            __syncwarp();

            const int rl   = wm * 32 + i * 16 + sr;          // local row in 128-tile
            const int ncol = n0 + wn * 64 + j * 16 + sc;     // global col

            size_t crow;
            if      (MODE == 3) crow = (size_t)grp * M + (size_t)(m0 + rl);
            else if (MODE == 4) crow = (size_t)grp + 8u * (size_t)(m0 + rl);
            else                crow = (size_t)(m0 + rl);
            float* Cp = C + crow * (size_t)N + ncol;

            float v[8];
            #pragma unroll
            for (int q = 0; q < 8; q++)
                v[q] = St[wid][sr][sc + q] + biasp[ncol + q];

            if (MODE == 4) {
                float4 c0 = *(float4*)Cp;
                float4 c1 = *(float4*)(Cp + 4);
                c0.x += 0.25f * v[0]; c0.y += 0.25f * v[1];
                c0.z += 0.25f * v[2]; c0.w += 0.25f * v[3];
                c1.x += 0.25f * v[4]; c1.y += 0.25f * v[5];
                c1.z += 0.25f * v[6]; c1.w += 0.25f * v[7];
                *(float4*)Cp       = c0;
                *(float4*)(Cp + 4) = c1;
            } else {
                #pragma unroll
                for (int q = 0; q < 8; q++) {
                    if (MODE == 2) v[q] = 0.5f * v[q];
                    if (MODE == 3) v[q] = 0.5f * v[q] * (1.0f + erff(v[q] * 0.70710678118654752f));
                }
                *(float4*)Cp       = make_float4(v[0], v[1], v[2], v[3]);
                *(float4*)(Cp + 4) = make_float4(v[4], v[5], v[6], v[7]);
            }
            __syncwarp();
        }
    }
}

// g1 = silu(g1) * g3, elementwise (float4)
__global__ void __launch_bounds__(256)
silu_mul_k(float* __restrict__ g1, const float* __restrict__ g3, size_t n4)
{
    size_t i = (size_t)blockIdx.x * blockDim.x + threadIdx.x;
    if (i < n4) {
        float4 a = ((float4*)g1)[i];
        float4 b = ((const float4*)g3)[i];
        a.x = (a.x / (1.f + expf(-a.x))) * b.x;
        a.y = (a.y / (1.f + expf(-a.y))) * b.y;
        a.z = (a.z / (1.f + expf(-a.z))) * b.z;
        a.w = (a.w / (1.f + expf(-a.w))) * b.w;
        ((float4*)g1)[i] = a;
    }
}

extern "C" void kernel_launch(void* const* d_in, const int* in_sizes, int n_in,
                              void* d_out, int out_size)
{
    const float* x   = (const float*)d_in[0];
    // d_in[1] = t_emb (unused by the reference)
    const float* sw1 = (const float*)d_in[2];
    const float* sb1 = (const float*)d_in[3];
    const float* sw3 = (const float*)d_in[4];
    const float* sb3 = (const float*)d_in[5];
    const float* sw2 = (const float*)d_in[6];
    const float* sb2 = (const float*)d_in[7];
    const float* w1  = (const float*)d_in[8];
    const float* b1  = (const float*)d_in[9];
    const float* w2  = (const float*)d_in[10];
    const float* b2  = (const float*)d_in[11];
    float* out = (float*)d_out;

    float *g1p, *g3p, *hp;
    cudaGetSymbolAddress((void**)&g1p, g_g1);
    cudaGetSymbolAddress((void**)&g3p, g_g3);
    cudaGetSymbolAddress((void**)&hp,  g_h);

    const dim3 blk(256);

    // Shared SwiGLU: g1 = x@sw1+sb1 ; g3 = x@sw3+sb3
    gemm_tc<0><<<dim3(HS / BN, NTOK / BM, 1), blk>>>(NTOK, HS, CDIM, x, sw1, sb1, g1p, 0);
    gemm_tc<0><<<dim3(HS / BN, NTOK / BM, 1), blk>>>(NTOK, HS, CDIM, x, sw3, sb3, g3p, 0);

    // g1 = silu(g1)*g3
    const size_t n4 = (size_t)NTOK * HS / 4;
    silu_mul_k<<<(unsigned)((n4 + 255) / 256), blk>>>(g1p, g3p, n4);

    // out = 0.5*(g1@sw2 + sb2)   (writes every output element)
    gemm_tc<2><<<dim3(CDIM / BN, NTOK / BM, 1), blk>>>(NTOK, CDIM, HS, g1p, sw2, sb2, out, 0);

    // Routed experts, k = 0 (phase 0) and k = 1 (phase 7)
    for (int phase = 0; phase <= 7; phase += 7) {
        gemm_tc<3><<<dim3(HR / BN, MPG / BM, 8), blk>>>(MPG, HR, CDIM, x, w1, b1, hp, phase);
        gemm_tc<4><<<dim3(CDIM / BN, MPG / BM, 8), blk>>>(MPG, CDIM, HR, hp, w2, b2, out, phase);
    }
}